// round 1
// baseline (speedup 1.0000x reference)
#include <cuda_runtime.h>

#define B_ 64
#define S_ 2048
#define D_ 512
#define U_ 512

// Scratch (allocation-free rule: __device__ globals)
__device__ float g_hd[B_ * U_];        // decoder projection + b2
__device__ float g_scores[B_ * S_];    // raw attention scores
__device__ float g_max[B_];
__device__ float g_invsum[B_];

__global__ void zero_out_kernel(float* out) {
    int i = blockIdx.x * blockDim.x + threadIdx.x;
    if (i < B_ * D_) out[i] = 0.0f;
}

// h_dec[b][u] = sum_k dec[b][k] * W2[k][u] + b2[u]
__global__ void hd_kernel(const float* __restrict__ dec,
                          const float* __restrict__ W2,
                          const float* __restrict__ b2) {
    __shared__ float ds[D_];
    int b = blockIdx.x;
    int u = threadIdx.x;
    ds[u] = dec[b * D_ + u];
    __syncthreads();
    float a = b2[u];
#pragma unroll 8
    for (int k = 0; k < D_; k++) a = fmaf(ds[k], W2[k * U_ + u], a);
    g_hd[b * U_ + u] = a;
}

// Main fused kernel: scores[m] = sum_u V[u] * tanh( (enc@W1)[m,u] + b1[u] + hd[b,u] )
// 128x128x16 tiling, 256 threads (16x16), 8x8 accumulators, double-buffered smem.
__global__ __launch_bounds__(256, 2)
void score_kernel(const float* __restrict__ enc,
                  const float* __restrict__ W1,
                  const float* __restrict__ b1,
                  const float* __restrict__ V) {
    __shared__ float As[2][16][128];  // [buf][k][m]  (transposed A)
    __shared__ float Bs[2][16][128];  // [buf][k][n]

    const int tid = threadIdx.x;
    const int tx = tid & 15;          // n-dim thread coord
    const int ty = tid >> 4;          // m-dim thread coord
    const int m0 = blockIdx.x * 128;  // global row base (flattened B*S)
    const int b = m0 >> 11;           // /2048

    // A tile load mapping: 128 rows x 16 cols = 512 float4, 2 per thread
    const int ar0 = tid >> 2;                 // 0..63
    const int ac0 = (tid & 3) * 4;            // 0,4,8,12
    const int ar1 = ar0 + 64;
    // B tile load mapping: 16 rows x 128 cols = 512 float4, 2 per thread
    const int br0 = tid >> 5;                 // 0..7
    const int bc0 = (tid & 31) * 4;           // 0..124
    const int br1 = br0 + 8;

    float scoreAcc[8];
#pragma unroll
    for (int i = 0; i < 8; i++) scoreAcc[i] = 0.0f;

    for (int nt = 0; nt < 4; ++nt) {
        const int n0 = nt * 128;
        float acc[8][8];
#pragma unroll
        for (int i = 0; i < 8; i++)
#pragma unroll
            for (int j = 0; j < 8; j++) acc[i][j] = 0.0f;

        // Prologue: load k-tile 0 into buffer 0
        {
            float4 a0 = *(const float4*)&enc[(size_t)(m0 + ar0) * D_ + ac0];
            float4 a1 = *(const float4*)&enc[(size_t)(m0 + ar1) * D_ + ac0];
            float4 bA = *(const float4*)&W1[(size_t)br0 * U_ + n0 + bc0];
            float4 bB = *(const float4*)&W1[(size_t)br1 * U_ + n0 + bc0];
            As[0][ac0 + 0][ar0] = a0.x; As[0][ac0 + 1][ar0] = a0.y;
            As[0][ac0 + 2][ar0] = a0.z; As[0][ac0 + 3][ar0] = a0.w;
            As[0][ac0 + 0][ar1] = a1.x; As[0][ac0 + 1][ar1] = a1.y;
            As[0][ac0 + 2][ar1] = a1.z; As[0][ac0 + 3][ar1] = a1.w;
            *(float4*)&Bs[0][br0][bc0] = bA;
            *(float4*)&Bs[0][br1][bc0] = bB;
        }
        __syncthreads();

        for (int kt = 0; kt < 32; ++kt) {
            const int cur = kt & 1;
            const int nxt = cur ^ 1;
            float4 a0, a1, bA, bB;
            const bool pf = (kt + 1 < 32);
            if (pf) {
                const int k0 = (kt + 1) * 16;
                a0 = *(const float4*)&enc[(size_t)(m0 + ar0) * D_ + k0 + ac0];
                a1 = *(const float4*)&enc[(size_t)(m0 + ar1) * D_ + k0 + ac0];
                bA = *(const float4*)&W1[(size_t)(k0 + br0) * U_ + n0 + bc0];
                bB = *(const float4*)&W1[(size_t)(k0 + br1) * U_ + n0 + bc0];
            }
#pragma unroll
            for (int k = 0; k < 16; k++) {
                float4 av0 = *(const float4*)&As[cur][k][ty * 8];
                float4 av1 = *(const float4*)&As[cur][k][ty * 8 + 4];
                float4 bv0 = *(const float4*)&Bs[cur][k][tx * 8];
                float4 bv1 = *(const float4*)&Bs[cur][k][tx * 8 + 4];
                float af[8] = {av0.x, av0.y, av0.z, av0.w, av1.x, av1.y, av1.z, av1.w};
                float bf[8] = {bv0.x, bv0.y, bv0.z, bv0.w, bv1.x, bv1.y, bv1.z, bv1.w};
#pragma unroll
                for (int i = 0; i < 8; i++)
#pragma unroll
                    for (int j = 0; j < 8; j++)
                        acc[i][j] = fmaf(af[i], bf[j], acc[i][j]);
            }
            if (pf) {
                As[nxt][ac0 + 0][ar0] = a0.x; As[nxt][ac0 + 1][ar0] = a0.y;
                As[nxt][ac0 + 2][ar0] = a0.z; As[nxt][ac0 + 3][ar0] = a0.w;
                As[nxt][ac0 + 0][ar1] = a1.x; As[nxt][ac0 + 1][ar1] = a1.y;
                As[nxt][ac0 + 2][ar1] = a1.z; As[nxt][ac0 + 3][ar1] = a1.w;
                *(float4*)&Bs[nxt][br0][bc0] = bA;
                *(float4*)&Bs[nxt][br1][bc0] = bB;
            }
            __syncthreads();
        }

        // Fused epilogue for this N-tile: bias + h_dec, tanh, dot with V
#pragma unroll
        for (int j = 0; j < 8; j++) {
            const int col = n0 + tx * 8 + j;
            const float c = b1[col] + g_hd[b * U_ + col];
            const float v = V[col];
#pragma unroll
            for (int i = 0; i < 8; i++) {
                scoreAcc[i] += v * tanhf(acc[i][j] + c);
            }
        }
    }

    // Reduce score partials across the 16 tx-threads sharing each row.
    // tid = ty*16 + tx -> tx == lane & 15, so xor over {8,4,2,1} stays in-half.
#pragma unroll
    for (int i = 0; i < 8; i++) {
        float s = scoreAcc[i];
        s += __shfl_xor_sync(0xffffffffu, s, 8, 32);
        s += __shfl_xor_sync(0xffffffffu, s, 4, 32);
        s += __shfl_xor_sync(0xffffffffu, s, 2, 32);
        s += __shfl_xor_sync(0xffffffffu, s, 1, 32);
        if (tx == 0) g_scores[m0 + ty * 8 + i] = s;
    }
}

// Per-batch softmax stats over S=2048 scores.
__global__ void stats_kernel() {
    const int b = blockIdx.x;
    const int tid = threadIdx.x;  // 256
    __shared__ float red[256];
    float m = -1e30f;
    for (int s = tid; s < S_; s += 256) m = fmaxf(m, g_scores[b * S_ + s]);
    red[tid] = m;
    __syncthreads();
    for (int o = 128; o; o >>= 1) {
        if (tid < o) red[tid] = fmaxf(red[tid], red[tid + o]);
        __syncthreads();
    }
    const float mx = red[0];
    __syncthreads();
    float sum = 0.0f;
    for (int s = tid; s < S_; s += 256) sum += expf(g_scores[b * S_ + s] - mx);
    red[tid] = sum;
    __syncthreads();
    for (int o = 128; o; o >>= 1) {
        if (tid < o) red[tid] += red[tid + o];
        __syncthreads();
    }
    if (tid == 0) {
        g_max[b] = mx;
        g_invsum[b] = 1.0f / red[0];
    }
}

// context[b][d] = sum_s attn[b][s] * enc[b][s][d]   (atomic partial sums)
__global__ void context_kernel(const float* __restrict__ enc,
                               float* __restrict__ out) {
    __shared__ float attn[128];
    const int b = blockIdx.y;
    const int s0 = blockIdx.x * 128;
    const int tid = threadIdx.x;  // 256
    if (tid < 128)
        attn[tid] = expf(g_scores[b * S_ + s0 + tid] - g_max[b]) * g_invsum[b];
    __syncthreads();
    float acc0 = 0.0f, acc1 = 0.0f;
    const float* base = enc + ((size_t)b * S_ + s0) * D_;
#pragma unroll 4
    for (int s = 0; s < 128; s++) {
        const float w = attn[s];
        acc0 = fmaf(w, base[(size_t)s * D_ + tid], acc0);
        acc1 = fmaf(w, base[(size_t)s * D_ + tid + 256], acc1);
    }
    atomicAdd(&out[b * D_ + tid], acc0);
    atomicAdd(&out[b * D_ + tid + 256], acc1);
}

extern "C" void kernel_launch(void* const* d_in, const int* in_sizes, int n_in,
                              void* d_out, int out_size) {
    const float* enc = (const float*)d_in[0];
    const float* dec = (const float*)d_in[1];
    const float* W1  = (const float*)d_in[2];
    const float* b1  = (const float*)d_in[3];
    const float* W2  = (const float*)d_in[4];
    const float* b2  = (const float*)d_in[5];
    const float* V   = (const float*)d_in[6];
    // d_in[7] = bv: scalar constant shift -> cancels in softmax, unused.
    float* out = (float*)d_out;

    zero_out_kernel<<<(B_ * D_ + 255) / 256, 256>>>(out);
    hd_kernel<<<B_, U_>>>(dec, W2, b2);
    score_kernel<<<(B_ * S_) / 128, 256>>>(enc, W1, b1, V);
    stats_kernel<<<B_, 256>>>();
    context_kernel<<<dim3(S_ / 128, B_), 256>>>(enc, out);
}

// round 3
// speedup vs baseline: 1.7032x; 1.7032x over previous
#include <cuda_runtime.h>
#include <cuda_fp16.h>
#include <cstdint>

#define B_ 64
#define S_ 2048
#define D_ 512
#define U_ 512
#define M_TOT (B_ * S_)

// ---------------- scratch (__device__ globals: allocation-free rule) ----------
__device__ float g_hd[B_ * U_];
__device__ float g_scores[B_ * S_];
__device__ float g_max[B_];
__device__ float g_invsum[B_];
__device__ float g_spart[4 * M_TOT];          // per-nblock score partials
__device__ __half g_w1t_hi[U_ * D_];          // [n][k] f16 hi
__device__ __half g_w1t_lo[U_ * D_];          // [n][k] f16 lo

// ---------------- helpers ----------------------------------------------------
__device__ __forceinline__ uint32_t smem_u32(const void* p) {
    uint32_t a;
    asm("{ .reg .u64 t; cvta.to.shared.u64 t, %1; cvt.u32.u64 %0, t; }" : "=r"(a) : "l"(p));
    return a;
}
__device__ __forceinline__ void ldsm4(uint32_t r[4], uint32_t addr) {
    asm volatile("ldmatrix.sync.aligned.m8n8.x4.shared.b16 {%0,%1,%2,%3}, [%4];"
                 : "=r"(r[0]), "=r"(r[1]), "=r"(r[2]), "=r"(r[3]) : "r"(addr));
}
__device__ __forceinline__ void mma16816(float c[4], const uint32_t a[4], const uint32_t* b) {
    asm volatile(
        "mma.sync.aligned.m16n8k16.row.col.f32.f16.f16.f32 "
        "{%0,%1,%2,%3}, {%4,%5,%6,%7}, {%8,%9}, {%0,%1,%2,%3};"
        : "+f"(c[0]), "+f"(c[1]), "+f"(c[2]), "+f"(c[3])
        : "r"(a[0]), "r"(a[1]), "r"(a[2]), "r"(a[3]), "r"(b[0]), "r"(b[1]));
}
__device__ __forceinline__ uint32_t h2u(half2 h) { return *reinterpret_cast<uint32_t*>(&h); }

// split 8 f32 -> 8 f16 hi + 8 f16 lo
__device__ __forceinline__ void split8(const float4& a, const float4& b, uint4& hi, uint4& lo) {
    half2 h0 = __floats2half2_rn(a.x, a.y);
    half2 h1 = __floats2half2_rn(a.z, a.w);
    half2 h2 = __floats2half2_rn(b.x, b.y);
    half2 h3 = __floats2half2_rn(b.z, b.w);
    float2 f0 = __half22float2(h0), f1 = __half22float2(h1);
    float2 f2 = __half22float2(h2), f3 = __half22float2(h3);
    half2 l0 = __floats2half2_rn(a.x - f0.x, a.y - f0.y);
    half2 l1 = __floats2half2_rn(a.z - f1.x, a.w - f1.y);
    half2 l2 = __floats2half2_rn(b.x - f2.x, b.y - f2.y);
    half2 l3 = __floats2half2_rn(b.z - f3.x, b.w - f3.y);
    hi = make_uint4(h2u(h0), h2u(h1), h2u(h2), h2u(h3));
    lo = make_uint4(h2u(l0), h2u(l1), h2u(l2), h2u(l3));
}

// ---------------- small kernels ----------------------------------------------
__global__ void zero_out_kernel(float* out) {
    int i = blockIdx.x * blockDim.x + threadIdx.x;
    if (i < B_ * D_) out[i] = 0.0f;
}

// W1 [K][N] f32 -> W1T hi/lo [N][K] f16 (transpose + 2-term split)
__global__ void w1split_kernel(const float* __restrict__ W1) {
    __shared__ float t[32][33];
    const int n0 = blockIdx.x * 32, k0 = blockIdx.y * 32;
    const int tx = threadIdx.x, ty = threadIdx.y;  // (32, 8)
#pragma unroll
    for (int r = 0; r < 4; r++)
        t[ty + r * 8][tx] = W1[(size_t)(k0 + ty + r * 8) * U_ + n0 + tx];
    __syncthreads();
#pragma unroll
    for (int r = 0; r < 4; r++) {
        const float x = t[tx][ty + r * 8];
        const __half hi = __float2half_rn(x);
        const __half lo = __float2half_rn(x - __half2float(hi));
        const size_t o = (size_t)(n0 + ty + r * 8) * D_ + k0 + tx;
        g_w1t_hi[o] = hi;
        g_w1t_lo[o] = lo;
    }
}

__global__ void hd_kernel(const float* __restrict__ dec,
                          const float* __restrict__ W2,
                          const float* __restrict__ b2) {
    __shared__ float ds[D_];
    int b = blockIdx.x;
    int u = threadIdx.x;
    ds[u] = dec[b * D_ + u];
    __syncthreads();
    float a = b2[u];
#pragma unroll 8
    for (int k = 0; k < D_; k++) a = fmaf(ds[k], W2[k * U_ + u], a);
    g_hd[b * U_ + u] = a;
}

// ---------------- main HMMA score kernel -------------------------------------
// partial[m] (over this nblock) = sum_n V[n] * tanh( (enc@W1)[m,n] + b1[n] + hd[b,n] )
#define RSTRIDE 80  // smem row stride (bytes): banks r*20 mod 32 all distinct

__global__ __launch_bounds__(256)
void score_mma_kernel(const float* __restrict__ enc,
                      const float* __restrict__ b1,
                      const float* __restrict__ V) {
    __shared__ __align__(16) char sA_hi[128 * RSTRIDE];
    __shared__ __align__(16) char sA_lo[128 * RSTRIDE];
    __shared__ __align__(16) char sB_hi[128 * RSTRIDE];
    __shared__ __align__(16) char sB_lo[128 * RSTRIDE];
    __shared__ float cpre[128], vpre[128], ssum[128];

    const int tid = threadIdx.x;
    const int lane = tid & 31;
    const int wid = tid >> 5;
    const int wm = wid >> 1;        // 0..3 (m)
    const int wn = wid & 1;         // 0..1 (n)
    const int m_base = wm * 32;
    const int n_base = wn * 64;
    const int m0 = blockIdx.x * 128;
    const int n0 = blockIdx.y * 128;
    const int b = m0 >> 11;

    // prologue smem setup
    if (tid < 128) {
        cpre[tid] = b1[n0 + tid] + g_hd[b * U_ + n0 + tid];
        vpre[tid] = V[n0 + tid];
        ssum[tid] = 0.0f;
    }

    // fill mappings
    const int arow = tid >> 1, ahalf = tid & 1;
    const float* gA = enc + (size_t)(m0 + arow) * D_ + ahalf * 16;
    const int brow = tid & 127;
    const __half* gB = ((tid < 128) ? g_w1t_hi : g_w1t_lo) + (size_t)(n0 + brow) * D_;
    char* sBmine = (tid < 128) ? sB_hi : sB_lo;
    char* aHiP = sA_hi + arow * RSTRIDE + ahalf * 32;
    char* aLoP = sA_lo + arow * RSTRIDE + ahalf * 32;
    char* bP = sBmine + brow * RSTRIDE;

    const uint32_t baseAh = smem_u32(sA_hi);
    const uint32_t baseAl = smem_u32(sA_lo);
    const uint32_t baseBh = smem_u32(sB_hi);
    const uint32_t baseBl = smem_u32(sB_lo);
    const uint32_t arow_off = ((lane & 7) + ((lane >> 3) & 1) * 8) * RSTRIDE + ((lane >> 4) & 1) * 16;
    const uint32_t brow_off = ((lane & 7) + ((lane >> 4) & 1) * 8) * RSTRIDE + ((lane >> 3) & 1) * 16;

    float acc[2][8][4];
#pragma unroll
    for (int mf = 0; mf < 2; mf++)
#pragma unroll
        for (int nf = 0; nf < 8; nf++)
#pragma unroll
            for (int r = 0; r < 4; r++) acc[mf][nf][r] = 0.0f;

    float4 pa[4];
    uint4 pb[4];
    // prologue loads (kt = 0)
#pragma unroll
    for (int j = 0; j < 4; j++) pa[j] = *(const float4*)(gA + j * 4);
#pragma unroll
    for (int j = 0; j < 4; j++) pb[j] = *(const uint4*)(gB + j * 8);
    {
        uint4 h0, l0, h1, l1;
        split8(pa[0], pa[1], h0, l0);
        split8(pa[2], pa[3], h1, l1);
        *(uint4*)(aHiP) = h0; *(uint4*)(aHiP + 16) = h1;
        *(uint4*)(aLoP) = l0; *(uint4*)(aLoP + 16) = l1;
#pragma unroll
        for (int j = 0; j < 4; j++) *(uint4*)(bP + j * 16) = pb[j];
    }
    __syncthreads();

    for (int kt = 0; kt < 16; ++kt) {
        // prefetch next k-chunk
        if (kt < 15) {
            const int kc = (kt + 1) * 32;
#pragma unroll
            for (int j = 0; j < 4; j++) pa[j] = *(const float4*)(gA + kc + j * 4);
#pragma unroll
            for (int j = 0; j < 4; j++) pb[j] = *(const uint4*)(gB + kc + j * 8);
        }

        // compute on current smem tiles
#pragma unroll
        for (int s = 0; s < 2; s++) {
            uint32_t ah[2][4], al[2][4];
            ldsm4(ah[0], baseAh + (m_base + 0) * RSTRIDE + s * 32 + arow_off);
            ldsm4(ah[1], baseAh + (m_base + 16) * RSTRIDE + s * 32 + arow_off);
            ldsm4(al[0], baseAl + (m_base + 0) * RSTRIDE + s * 32 + arow_off);
            ldsm4(al[1], baseAl + (m_base + 16) * RSTRIDE + s * 32 + arow_off);
#pragma unroll
            for (int np = 0; np < 4; np++) {
                uint32_t bh[4], bl[4];
                ldsm4(bh, baseBh + (n_base + np * 16) * RSTRIDE + s * 32 + brow_off);
                ldsm4(bl, baseBl + (n_base + np * 16) * RSTRIDE + s * 32 + brow_off);
#pragma unroll
                for (int mf = 0; mf < 2; mf++) {
                    mma16816(acc[mf][2 * np + 0], ah[mf], bh);
                    mma16816(acc[mf][2 * np + 0], ah[mf], bl);
                    mma16816(acc[mf][2 * np + 0], al[mf], bh);
                    mma16816(acc[mf][2 * np + 1], ah[mf], bh + 2);
                    mma16816(acc[mf][2 * np + 1], ah[mf], bl + 2);
                    mma16816(acc[mf][2 * np + 1], al[mf], bh + 2);
                }
            }
        }
        __syncthreads();

        if (kt < 15) {
            uint4 h0, l0, h1, l1;
            split8(pa[0], pa[1], h0, l0);
            split8(pa[2], pa[3], h1, l1);
            *(uint4*)(aHiP) = h0; *(uint4*)(aHiP + 16) = h1;
            *(uint4*)(aLoP) = l0; *(uint4*)(aLoP + 16) = l1;
#pragma unroll
            for (int j = 0; j < 4; j++) *(uint4*)(bP + j * 16) = pb[j];
            __syncthreads();
        }
    }

    // ---- epilogue: tanh + V-dot, reduce to row partials ----
    const int g = lane >> 2, tg = lane & 3;
    float p[2][2] = {{0.0f, 0.0f}, {0.0f, 0.0f}};
#pragma unroll
    for (int mf = 0; mf < 2; mf++) {
#pragma unroll
        for (int nf = 0; nf < 8; nf++) {
            const int c0 = n_base + nf * 8 + tg * 2;
            const float v0 = vpre[c0], v1 = vpre[c0 + 1];
            const float k0 = cpre[c0], k1 = cpre[c0 + 1];
            p[mf][0] += v0 * tanhf(acc[mf][nf][0] + k0) + v1 * tanhf(acc[mf][nf][1] + k1);
            p[mf][1] += v0 * tanhf(acc[mf][nf][2] + k0) + v1 * tanhf(acc[mf][nf][3] + k1);
        }
    }
#pragma unroll
    for (int mf = 0; mf < 2; mf++)
#pragma unroll
        for (int h = 0; h < 2; h++) {
            float s = p[mf][h];
            s += __shfl_xor_sync(0xffffffffu, s, 1);
            s += __shfl_xor_sync(0xffffffffu, s, 2);
            if (tg == 0) atomicAdd(&ssum[wm * 32 + mf * 16 + h * 8 + g], s);
        }
    __syncthreads();
    if (tid < 128) g_spart[(size_t)blockIdx.y * M_TOT + m0 + tid] = ssum[tid];
}

// ---------------- softmax stats (combines 4 partials) + context --------------
__global__ void stats_kernel() {
    const int b = blockIdx.x;
    const int tid = threadIdx.x;  // 256
    __shared__ float red[256];
    float m = -1e30f;
    for (int s = tid; s < S_; s += 256) {
        const int i = b * S_ + s;
        const float v = g_spart[i] + g_spart[M_TOT + i] + g_spart[2 * M_TOT + i] + g_spart[3 * M_TOT + i];
        g_scores[i] = v;
        m = fmaxf(m, v);
    }
    red[tid] = m;
    __syncthreads();
    for (int o = 128; o; o >>= 1) {
        if (tid < o) red[tid] = fmaxf(red[tid], red[tid + o]);
        __syncthreads();
    }
    const float mx = red[0];
    __syncthreads();
    float sum = 0.0f;
    for (int s = tid; s < S_; s += 256) sum += expf(g_scores[b * S_ + s] - mx);
    red[tid] = sum;
    __syncthreads();
    for (int o = 128; o; o >>= 1) {
        if (tid < o) red[tid] += red[tid + o];
        __syncthreads();
    }
    if (tid == 0) {
        g_max[b] = mx;
        g_invsum[b] = 1.0f / red[0];
    }
}

__global__ void context_kernel(const float* __restrict__ enc,
                               float* __restrict__ out) {
    __shared__ float attn[128];
    const int b = blockIdx.y;
    const int s0 = blockIdx.x * 128;
    const int tid = threadIdx.x;  // 256
    if (tid < 128)
        attn[tid] = expf(g_scores[b * S_ + s0 + tid] - g_max[b]) * g_invsum[b];
    __syncthreads();
    float acc0 = 0.0f, acc1 = 0.0f;
    const float* base = enc + ((size_t)b * S_ + s0) * D_;
#pragma unroll 4
    for (int s = 0; s < 128; s++) {
        const float w = attn[s];
        acc0 = fmaf(w, base[(size_t)s * D_ + tid], acc0);
        acc1 = fmaf(w, base[(size_t)s * D_ + tid + 256], acc1);
    }
    atomicAdd(&out[b * D_ + tid], acc0);
    atomicAdd(&out[b * D_ + tid + 256], acc1);
}

// ---------------- launch ------------------------------------------------------
extern "C" void kernel_launch(void* const* d_in, const int* in_sizes, int n_in,
                              void* d_out, int out_size) {
    const float* enc = (const float*)d_in[0];
    const float* dec = (const float*)d_in[1];
    const float* W1  = (const float*)d_in[2];
    const float* b1  = (const float*)d_in[3];
    const float* W2  = (const float*)d_in[4];
    const float* b2  = (const float*)d_in[5];
    const float* V   = (const float*)d_in[6];
    // d_in[7] = bv: constant shift, cancels in softmax.
    float* out = (float*)d_out;

    w1split_kernel<<<dim3(16, 16), dim3(32, 8)>>>(W1);
    zero_out_kernel<<<(B_ * D_ + 255) / 256, 256>>>(out);
    hd_kernel<<<B_, U_>>>(dec, W2, b2);
    score_mma_kernel<<<dim3(M_TOT / 128, 4), 256>>>(enc, b1, V);
    stats_kernel<<<B_, 256>>>();
    context_kernel<<<dim3(S_ / 128, B_), 256>>>(enc, out);
}

// round 4
// speedup vs baseline: 3.4093x; 2.0017x over previous
#include <cuda_runtime.h>
#include <cuda_fp16.h>
#include <cstdint>

#define B_ 64
#define S_ 2048
#define D_ 512
#define U_ 512
#define M_TOT (B_ * S_)

// ---------------- scratch (__device__ globals: allocation-free rule) ----------
__device__ float g_hd[B_ * U_];
__device__ float g_scores[B_ * S_];
__device__ float g_max[B_];
__device__ float g_invsum[B_];
__device__ float g_spart[4 * M_TOT];          // per-nblock score partials
__device__ __half g_w1t[U_ * D_];             // [n][k] f16

// ---------------- helpers ----------------------------------------------------
__device__ __forceinline__ uint32_t smem_u32(const void* p) {
    uint32_t a;
    asm("{ .reg .u64 t; cvta.to.shared.u64 t, %1; cvt.u32.u64 %0, t; }" : "=r"(a) : "l"(p));
    return a;
}
__device__ __forceinline__ void ldsm4(uint32_t r[4], uint32_t addr) {
    asm volatile("ldmatrix.sync.aligned.m8n8.x4.shared.b16 {%0,%1,%2,%3}, [%4];"
                 : "=r"(r[0]), "=r"(r[1]), "=r"(r[2]), "=r"(r[3]) : "r"(addr));
}
__device__ __forceinline__ void mma16816(float c[4], const uint32_t a[4], const uint32_t* b) {
    asm volatile(
        "mma.sync.aligned.m16n8k16.row.col.f32.f16.f16.f32 "
        "{%0,%1,%2,%3}, {%4,%5,%6,%7}, {%8,%9}, {%0,%1,%2,%3};"
        : "+f"(c[0]), "+f"(c[1]), "+f"(c[2]), "+f"(c[3])
        : "r"(a[0]), "r"(a[1]), "r"(a[2]), "r"(a[3]), "r"(b[0]), "r"(b[1]));
}
__device__ __forceinline__ uint32_t h2u(half2 h) { return *reinterpret_cast<uint32_t*>(&h); }

// convert 8 f32 -> 8 f16 (one uint4)
__device__ __forceinline__ uint4 cvt8(const float4& a, const float4& b) {
    half2 h0 = __floats2half2_rn(a.x, a.y);
    half2 h1 = __floats2half2_rn(a.z, a.w);
    half2 h2 = __floats2half2_rn(b.x, b.y);
    half2 h3 = __floats2half2_rn(b.z, b.w);
    return make_uint4(h2u(h0), h2u(h1), h2u(h2), h2u(h3));
}

// ---------------- small kernels ----------------------------------------------
__global__ void zero_out_kernel(float* out) {
    int i = blockIdx.x * blockDim.x + threadIdx.x;
    if (i < B_ * D_) out[i] = 0.0f;
}

// W1 [K][N] f32 -> W1T [N][K] f16 (transpose + convert)
__global__ void w1split_kernel(const float* __restrict__ W1) {
    __shared__ float t[32][33];
    const int n0 = blockIdx.x * 32, k0 = blockIdx.y * 32;
    const int tx = threadIdx.x, ty = threadIdx.y;  // (32, 8)
#pragma unroll
    for (int r = 0; r < 4; r++)
        t[ty + r * 8][tx] = W1[(size_t)(k0 + ty + r * 8) * U_ + n0 + tx];
    __syncthreads();
#pragma unroll
    for (int r = 0; r < 4; r++) {
        const float x = t[tx][ty + r * 8];
        g_w1t[(size_t)(n0 + ty + r * 8) * D_ + k0 + tx] = __float2half_rn(x);
    }
}

__global__ void hd_kernel(const float* __restrict__ dec,
                          const float* __restrict__ W2,
                          const float* __restrict__ b2) {
    __shared__ float ds[D_];
    int b = blockIdx.x;
    int u = threadIdx.x;
    ds[u] = dec[b * D_ + u];
    __syncthreads();
    float a = b2[u];
#pragma unroll 8
    for (int k = 0; k < D_; k++) a = fmaf(ds[k], W2[k * U_ + u], a);
    g_hd[b * U_ + u] = a;
}

// ---------------- main HMMA score kernel (pure fp16, 1-term) -----------------
// partial[m] (this nblock) = sum_n V[n] * tanh( (enc@W1)[m,n] + b1[n] + hd[b,n] )
#define RSTRIDE 80  // smem row stride (bytes): banks r*20 mod 32 all distinct

__global__ __launch_bounds__(256, 2)
void score_mma_kernel(const float* __restrict__ enc,
                      const float* __restrict__ b1,
                      const float* __restrict__ V) {
    __shared__ __align__(16) char sA[128 * RSTRIDE];
    __shared__ __align__(16) char sB[128 * RSTRIDE];
    __shared__ float cpre[128], vpre[128], ssum[128];

    const int tid = threadIdx.x;
    const int lane = tid & 31;
    const int wid = tid >> 5;
    const int wm = wid >> 1;        // 0..3 (m)
    const int wn = wid & 1;         // 0..1 (n)
    const int m_base = wm * 32;
    const int n_base = wn * 64;
    const int n0 = blockIdx.x * 128;   // nblock fastest -> 4 nblocks of same M co-resident
    const int m0 = blockIdx.y * 128;
    const int b = m0 >> 11;

    if (tid < 128) {
        cpre[tid] = b1[n0 + tid] + g_hd[b * U_ + n0 + tid];
        vpre[tid] = V[n0 + tid];
        ssum[tid] = 0.0f;
    }

    // fill mappings
    const int arow = tid >> 1, ahalf = tid & 1;           // A: 128 rows x 32 k (f32 src)
    const float* gA = enc + (size_t)(m0 + arow) * D_ + ahalf * 16;
    char* aP = sA + arow * RSTRIDE + ahalf * 32;
    const int brow = tid >> 1, bhalf = tid & 1;           // B: 128 rows x 32 k (f16 src)
    const __half* gB = g_w1t + (size_t)(n0 + brow) * D_ + bhalf * 16;
    char* bP = sB + brow * RSTRIDE + bhalf * 32;

    const uint32_t baseA = smem_u32(sA);
    const uint32_t baseB = smem_u32(sB);
    const uint32_t arow_off = ((lane & 7) + ((lane >> 3) & 1) * 8) * RSTRIDE + ((lane >> 4) & 1) * 16;
    const uint32_t brow_off = ((lane & 7) + ((lane >> 4) & 1) * 8) * RSTRIDE + ((lane >> 3) & 1) * 16;

    float acc[2][8][4];
#pragma unroll
    for (int mf = 0; mf < 2; mf++)
#pragma unroll
        for (int nf = 0; nf < 8; nf++)
#pragma unroll
            for (int r = 0; r < 4; r++) acc[mf][nf][r] = 0.0f;

    float4 pa[4];
    uint4 pb[2];
    // prologue loads (kt = 0)
#pragma unroll
    for (int j = 0; j < 4; j++) pa[j] = *(const float4*)(gA + j * 4);
#pragma unroll
    for (int j = 0; j < 2; j++) pb[j] = *(const uint4*)(gB + j * 8);
    {
        *(uint4*)(aP) = cvt8(pa[0], pa[1]);
        *(uint4*)(aP + 16) = cvt8(pa[2], pa[3]);
        *(uint4*)(bP) = pb[0];
        *(uint4*)(bP + 16) = pb[1];
    }
    __syncthreads();

    for (int kt = 0; kt < 16; ++kt) {
        // prefetch next k-chunk into registers
        if (kt < 15) {
            const int kc = (kt + 1) * 32;
#pragma unroll
            for (int j = 0; j < 4; j++) pa[j] = *(const float4*)(gA + kc + j * 4);
#pragma unroll
            for (int j = 0; j < 2; j++) pb[j] = *(const uint4*)(gB + kc + j * 8);
        }

        // compute on current smem tiles
#pragma unroll
        for (int s = 0; s < 2; s++) {
            uint32_t ah[2][4];
            ldsm4(ah[0], baseA + (m_base + 0) * RSTRIDE + s * 32 + arow_off);
            ldsm4(ah[1], baseA + (m_base + 16) * RSTRIDE + s * 32 + arow_off);
#pragma unroll
            for (int np = 0; np < 4; np++) {
                uint32_t bh[4];
                ldsm4(bh, baseB + (n_base + np * 16) * RSTRIDE + s * 32 + brow_off);
#pragma unroll
                for (int mf = 0; mf < 2; mf++) {
                    mma16816(acc[mf][2 * np + 0], ah[mf], bh);
                    mma16816(acc[mf][2 * np + 1], ah[mf], bh + 2);
                }
            }
        }
        __syncthreads();

        if (kt < 15) {
            *(uint4*)(aP) = cvt8(pa[0], pa[1]);
            *(uint4*)(aP + 16) = cvt8(pa[2], pa[3]);
            *(uint4*)(bP) = pb[0];
            *(uint4*)(bP + 16) = pb[1];
            __syncthreads();
        }
    }

    // ---- epilogue: tanh + V-dot, reduce to row partials ----
    const int g = lane >> 2, tg = lane & 3;
    float p[2][2] = {{0.0f, 0.0f}, {0.0f, 0.0f}};
#pragma unroll
    for (int mf = 0; mf < 2; mf++) {
#pragma unroll
        for (int nf = 0; nf < 8; nf++) {
            const int c0 = n_base + nf * 8 + tg * 2;
            const float v0 = vpre[c0], v1 = vpre[c0 + 1];
            const float k0 = cpre[c0], k1 = cpre[c0 + 1];
            p[mf][0] += v0 * tanhf(acc[mf][nf][0] + k0) + v1 * tanhf(acc[mf][nf][1] + k1);
            p[mf][1] += v0 * tanhf(acc[mf][nf][2] + k0) + v1 * tanhf(acc[mf][nf][3] + k1);
        }
    }
#pragma unroll
    for (int mf = 0; mf < 2; mf++)
#pragma unroll
        for (int h = 0; h < 2; h++) {
            float s = p[mf][h];
            s += __shfl_xor_sync(0xffffffffu, s, 1);
            s += __shfl_xor_sync(0xffffffffu, s, 2);
            if (tg == 0) atomicAdd(&ssum[wm * 32 + mf * 16 + h * 8 + g], s);
        }
    __syncthreads();
    if (tid < 128) g_spart[(size_t)blockIdx.x * M_TOT + m0 + tid] = ssum[tid];
}

// ---------------- softmax stats (combines 4 partials) + context --------------
__global__ void stats_kernel() {
    const int b = blockIdx.x;
    const int tid = threadIdx.x;  // 256
    __shared__ float red[256];
    float m = -1e30f;
    for (int s = tid; s < S_; s += 256) {
        const int i = b * S_ + s;
        const float v = g_spart[i] + g_spart[M_TOT + i] + g_spart[2 * M_TOT + i] + g_spart[3 * M_TOT + i];
        g_scores[i] = v;
        m = fmaxf(m, v);
    }
    red[tid] = m;
    __syncthreads();
    for (int o = 128; o; o >>= 1) {
        if (tid < o) red[tid] = fmaxf(red[tid], red[tid + o]);
        __syncthreads();
    }
    const float mx = red[0];
    __syncthreads();
    float sum = 0.0f;
    for (int s = tid; s < S_; s += 256) sum += expf(g_scores[b * S_ + s] - mx);
    red[tid] = sum;
    __syncthreads();
    for (int o = 128; o; o >>= 1) {
        if (tid < o) red[tid] += red[tid + o];
        __syncthreads();
    }
    if (tid == 0) {
        g_max[b] = mx;
        g_invsum[b] = 1.0f / red[0];
    }
}

__global__ void context_kernel(const float* __restrict__ enc,
                               float* __restrict__ out) {
    __shared__ float attn[128];
    const int b = blockIdx.y;
    const int s0 = blockIdx.x * 128;
    const int tid = threadIdx.x;  // 256
    if (tid < 128)
        attn[tid] = expf(g_scores[b * S_ + s0 + tid] - g_max[b]) * g_invsum[b];
    __syncthreads();
    float acc0 = 0.0f, acc1 = 0.0f;
    const float* base = enc + ((size_t)b * S_ + s0) * D_;
#pragma unroll 4
    for (int s = 0; s < 128; s++) {
        const float w = attn[s];
        acc0 = fmaf(w, base[(size_t)s * D_ + tid], acc0);
        acc1 = fmaf(w, base[(size_t)s * D_ + tid + 256], acc1);
    }
    atomicAdd(&out[b * D_ + tid], acc0);
    atomicAdd(&out[b * D_ + tid + 256], acc1);
}

// ---------------- launch ------------------------------------------------------
extern "C" void kernel_launch(void* const* d_in, const int* in_sizes, int n_in,
                              void* d_out, int out_size) {
    const float* enc = (const float*)d_in[0];
    const float* dec = (const float*)d_in[1];
    const float* W1  = (const float*)d_in[2];
    const float* b1  = (const float*)d_in[3];
    const float* W2  = (const float*)d_in[4];
    const float* b2  = (const float*)d_in[5];
    const float* V   = (const float*)d_in[6];
    // d_in[7] = bv: constant shift, cancels in softmax.
    float* out = (float*)d_out;

    w1split_kernel<<<dim3(16, 16), dim3(32, 8)>>>(W1);
    zero_out_kernel<<<(B_ * D_ + 255) / 256, 256>>>(out);
    hd_kernel<<<B_, U_>>>(dec, W2, b2);
    score_mma_kernel<<<dim3(4, M_TOT / 128), 256>>>(enc, b1, V);
    stats_kernel<<<B_, 256>>>();
    context_kernel<<<dim3(S_ / 128, B_), 256>>>(enc, out);
}

// round 5
// speedup vs baseline: 3.7897x; 1.1116x over previous
#include <cuda_runtime.h>
#include <cuda_fp16.h>
#include <cstdint>

#define B_ 64
#define S_ 2048
#define D_ 512
#define U_ 512
#define M_TOT (B_ * S_)
#define MB_CNT (M_TOT / 32)   // 4096 m32-blocks

// ---------------- scratch (__device__ globals: allocation-free rule) ----------
__device__ float g_hd[B_ * U_];
__device__ float g_scores[M_TOT];
__device__ float g_max[B_];
__device__ float g_invsum[B_];
__device__ float g_spart[4 * M_TOT];
__device__ __half g_w1t[U_ * D_];                  // [n][k] f16
__device__ uint4 g_encfrag[(size_t)MB_CNT * 2048]; // [mb][k16(32)][g(2)][lane(32)]
__device__ uint4 g_w1frag[8 * 4096];               // [nb][k16(32)][g(4)][lane(32)]

// ---------------- helpers ----------------------------------------------------
__device__ __forceinline__ uint32_t smem_u32(const void* p) {
    uint32_t a;
    asm("{ .reg .u64 t; cvta.to.shared.u64 t, %1; cvt.u32.u64 %0, t; }" : "=r"(a) : "l"(p));
    return a;
}
__device__ __forceinline__ void ldsm4(uint32_t r[4], uint32_t addr) {
    asm volatile("ldmatrix.sync.aligned.m8n8.x4.shared.b16 {%0,%1,%2,%3}, [%4];"
                 : "=r"(r[0]), "=r"(r[1]), "=r"(r[2]), "=r"(r[3]) : "r"(addr));
}
__device__ __forceinline__ void mma16816(float c[4], const uint32_t* a, const uint32_t* b) {
    asm volatile(
        "mma.sync.aligned.m16n8k16.row.col.f32.f16.f16.f32 "
        "{%0,%1,%2,%3}, {%4,%5,%6,%7}, {%8,%9}, {%0,%1,%2,%3};"
        : "+f"(c[0]), "+f"(c[1]), "+f"(c[2]), "+f"(c[3])
        : "r"(a[0]), "r"(a[1]), "r"(a[2]), "r"(a[3]), "r"(b[0]), "r"(b[1]));
}
__device__ __forceinline__ uint32_t h2u(half2 h) { return *reinterpret_cast<uint32_t*>(&h); }

// ---------------- small kernels ----------------------------------------------
__global__ void zero_out_kernel(float* out) {
    int i = blockIdx.x * blockDim.x + threadIdx.x;
    if (i < B_ * D_) out[i] = 0.0f;
}

// W1 [K][N] f32 -> W1T [N][K] f16 (transpose + convert)
__global__ void w1split_kernel(const float* __restrict__ W1) {
    __shared__ float t[32][33];
    const int n0 = blockIdx.x * 32, k0 = blockIdx.y * 32;
    const int tx = threadIdx.x, ty = threadIdx.y;  // (32, 8)
#pragma unroll
    for (int r = 0; r < 4; r++)
        t[ty + r * 8][tx] = W1[(size_t)(k0 + ty + r * 8) * U_ + n0 + tx];
    __syncthreads();
#pragma unroll
    for (int r = 0; r < 4; r++) {
        const float x = t[tx][ty + r * 8];
        g_w1t[(size_t)(n0 + ty + r * 8) * D_ + k0 + tx] = __float2half_rn(x);
    }
}

__global__ void hd_kernel(const float* __restrict__ dec,
                          const float* __restrict__ W2,
                          const float* __restrict__ b2) {
    __shared__ float ds[D_];
    int b = blockIdx.x;
    int u = threadIdx.x;
    ds[u] = dec[b * D_ + u];
    __syncthreads();
    float a = b2[u];
#pragma unroll 8
    for (int k = 0; k < D_; k++) a = fmaf(ds[k], W2[k * U_ + u], a);
    g_hd[b * U_ + u] = a;
}

// ---------------- prepass: enc f32 -> A fragments (f16) ----------------------
// Replicates round-4 smem fill + ldsm addressing exactly; stores lane regs.
__global__ __launch_bounds__(256)
void encfrag_kernel(const float* __restrict__ enc) {
    __shared__ __align__(16) char sA[8][32 * 80];
    const int lane = threadIdx.x & 31, wid = threadIdx.x >> 5;
    const int mb = blockIdx.x * 8 + wid;
    const float* src = enc + (size_t)mb * 32 * D_;
    char* ws = sA[wid];
    const uint32_t base = smem_u32(ws);
    const uint32_t aoff = ((lane & 7) + ((lane >> 3) & 1) * 8) * 80 + ((lane >> 4) & 1) * 16;
    const int r0 = lane >> 3;        // 0..3
    const int c0 = (lane & 7) * 4;   // f32 col within k32 chunk

    for (int kt = 0; kt < 16; kt++) {
        const int k0 = kt * 32;
#pragma unroll
        for (int i = 0; i < 8; i++) {
            const int row = r0 + i * 4;
            float4 f = *(const float4*)(src + (size_t)row * D_ + k0 + c0);
            half2 h0 = __floats2half2_rn(f.x, f.y);
            half2 h1 = __floats2half2_rn(f.z, f.w);
            *(uint2*)(ws + row * 80 + c0 * 2) = make_uint2(h2u(h0), h2u(h1));
        }
        __syncwarp();
#pragma unroll
        for (int s = 0; s < 2; s++)
#pragma unroll
            for (int g = 0; g < 2; g++) {
                uint32_t r[4];
                ldsm4(r, base + g * 16 * 80 + s * 32 + aoff);
                g_encfrag[(((size_t)mb * 32 + kt * 2 + s) * 2 + g) * 32 + lane] =
                    make_uint4(r[0], r[1], r[2], r[3]);
            }
        __syncwarp();
    }
}

// ---------------- prepass: W1T f16 -> B fragments ----------------------------
__global__ void w1frag_kernel() {
    __shared__ __align__(16) char sB[64 * 80];
    const int lane = threadIdx.x;   // 32 threads
    const int nb = blockIdx.x;      // 0..7
    const uint32_t base = smem_u32(sB);
    const uint32_t boff = ((lane & 7) + ((lane >> 4) & 1) * 8) * 80 + ((lane >> 3) & 1) * 16;
    const int r0 = lane >> 3;       // 0..3
    const int c0 = (lane & 7) * 4;  // half col within k32 chunk

    for (int kt = 0; kt < 16; kt++) {
        const int k0 = kt * 32;
#pragma unroll
        for (int i = 0; i < 16; i++) {
            const int row = r0 + i * 4;   // 0..63
            uint2 v = *(const uint2*)(g_w1t + (size_t)(nb * 64 + row) * D_ + k0 + c0);
            *(uint2*)(sB + row * 80 + c0 * 2) = v;
        }
        __syncwarp();
#pragma unroll
        for (int s = 0; s < 2; s++)
#pragma unroll
            for (int g = 0; g < 4; g++) {
                uint32_t r[4];
                ldsm4(r, base + g * 16 * 80 + s * 32 + boff);
                g_w1frag[((nb * 32 + kt * 2 + s) * 4 + g) * 32 + lane] =
                    make_uint4(r[0], r[1], r[2], r[3]);
            }
        __syncwarp();
    }
}

// ---------------- main score kernel: pure LDG + HMMA, no smem tiles ----------
__global__ __launch_bounds__(256, 2)
void score_frag_kernel(const float* __restrict__ b1, const float* __restrict__ V) {
    __shared__ float cpre[128], vpre[128], ssum[128];
    const int tid = threadIdx.x, lane = tid & 31, wid = tid >> 5;
    const int wm = wid >> 1, wn = wid & 1;
    const int n0 = blockIdx.x * 128, m0 = blockIdx.y * 128, b = m0 >> 11;

    if (tid < 128) {
        cpre[tid] = b1[n0 + tid] + g_hd[b * U_ + n0 + tid];
        vpre[tid] = V[n0 + tid];
        ssum[tid] = 0.0f;
    }

    const int mb = blockIdx.y * 4 + wm;
    const int nb = blockIdx.x * 2 + wn;
    const uint4* Ap = g_encfrag + (size_t)mb * 2048 + lane;  // +k*64, +g*32
    const uint4* Bp = g_w1frag + (size_t)nb * 4096 + lane;   // +k*128, +g*32

    float acc[2][8][4] = {};

    uint4 a0 = Ap[0], a1 = Ap[32];
    uint4 f0 = Bp[0], f1 = Bp[32], f2 = Bp[64], f3 = Bp[96];

#pragma unroll 2
    for (int k = 0; k < 32; k++) {
        uint4 na0, na1, nf0, nf1, nf2, nf3;
        if (k < 31) {
            const uint4* An = Ap + (size_t)(k + 1) * 64;
            const uint4* Bn = Bp + (size_t)(k + 1) * 128;
            na0 = An[0]; na1 = An[32];
            nf0 = Bn[0]; nf1 = Bn[32]; nf2 = Bn[64]; nf3 = Bn[96];
        }
        {
            const uint32_t* A0 = (const uint32_t*)&a0;
            const uint32_t* A1 = (const uint32_t*)&a1;
            const uint32_t* Bq0 = (const uint32_t*)&f0;
            const uint32_t* Bq1 = (const uint32_t*)&f1;
            const uint32_t* Bq2 = (const uint32_t*)&f2;
            const uint32_t* Bq3 = (const uint32_t*)&f3;
            mma16816(acc[0][0], A0, Bq0); mma16816(acc[0][1], A0, Bq0 + 2);
            mma16816(acc[1][0], A1, Bq0); mma16816(acc[1][1], A1, Bq0 + 2);
            mma16816(acc[0][2], A0, Bq1); mma16816(acc[0][3], A0, Bq1 + 2);
            mma16816(acc[1][2], A1, Bq1); mma16816(acc[1][3], A1, Bq1 + 2);
            mma16816(acc[0][4], A0, Bq2); mma16816(acc[0][5], A0, Bq2 + 2);
            mma16816(acc[1][4], A1, Bq2); mma16816(acc[1][5], A1, Bq2 + 2);
            mma16816(acc[0][6], A0, Bq3); mma16816(acc[0][7], A0, Bq3 + 2);
            mma16816(acc[1][6], A1, Bq3); mma16816(acc[1][7], A1, Bq3 + 2);
        }
        if (k < 31) {
            a0 = na0; a1 = na1;
            f0 = nf0; f1 = nf1; f2 = nf2; f3 = nf3;
        }
    }

    __syncthreads();  // ssum init complete; all warps done

    // ---- epilogue: tanh + V-dot, reduce to row partials ----
    const int g = lane >> 2, tg = lane & 3;
    const int n_base = wn * 64;
    float p[2][2] = {{0.0f, 0.0f}, {0.0f, 0.0f}};
#pragma unroll
    for (int mf = 0; mf < 2; mf++) {
#pragma unroll
        for (int nf = 0; nf < 8; nf++) {
            const int c0 = n_base + nf * 8 + tg * 2;
            const float v0 = vpre[c0], v1 = vpre[c0 + 1];
            const float k0 = cpre[c0], k1 = cpre[c0 + 1];
            p[mf][0] += v0 * tanhf(acc[mf][nf][0] + k0) + v1 * tanhf(acc[mf][nf][1] + k1);
            p[mf][1] += v0 * tanhf(acc[mf][nf][2] + k0) + v1 * tanhf(acc[mf][nf][3] + k1);
        }
    }
#pragma unroll
    for (int mf = 0; mf < 2; mf++)
#pragma unroll
        for (int h = 0; h < 2; h++) {
            float s = p[mf][h];
            s += __shfl_xor_sync(0xffffffffu, s, 1);
            s += __shfl_xor_sync(0xffffffffu, s, 2);
            if (tg == 0) atomicAdd(&ssum[wm * 32 + mf * 16 + h * 8 + g], s);
        }
    __syncthreads();
    if (tid < 128) g_spart[(size_t)blockIdx.x * M_TOT + m0 + tid] = ssum[tid];
}

// ---------------- softmax stats (combines 4 partials) + context --------------
__global__ void stats_kernel() {
    const int b = blockIdx.x;
    const int tid = threadIdx.x;  // 256
    __shared__ float red[256];
    float m = -1e30f;
    for (int s = tid; s < S_; s += 256) {
        const int i = b * S_ + s;
        const float v = g_spart[i] + g_spart[M_TOT + i] + g_spart[2 * M_TOT + i] + g_spart[3 * M_TOT + i];
        g_scores[i] = v;
        m = fmaxf(m, v);
    }
    red[tid] = m;
    __syncthreads();
    for (int o = 128; o; o >>= 1) {
        if (tid < o) red[tid] = fmaxf(red[tid], red[tid + o]);
        __syncthreads();
    }
    const float mx = red[0];
    __syncthreads();
    float sum = 0.0f;
    for (int s = tid; s < S_; s += 256) sum += expf(g_scores[b * S_ + s] - mx);
    red[tid] = sum;
    __syncthreads();
    for (int o = 128; o; o >>= 1) {
        if (tid < o) red[tid] += red[tid + o];
        __syncthreads();
    }
    if (tid == 0) {
        g_max[b] = mx;
        g_invsum[b] = 1.0f / red[0];
    }
}

__global__ void context_kernel(const float* __restrict__ enc,
                               float* __restrict__ out) {
    __shared__ float attn[128];
    const int b = blockIdx.y;
    const int s0 = blockIdx.x * 128;
    const int tid = threadIdx.x;  // 256
    if (tid < 128)
        attn[tid] = expf(g_scores[b * S_ + s0 + tid] - g_max[b]) * g_invsum[b];
    __syncthreads();
    float acc0 = 0.0f, acc1 = 0.0f;
    const float* base = enc + ((size_t)b * S_ + s0) * D_;
#pragma unroll 4
    for (int s = 0; s < 128; s++) {
        const float w = attn[s];
        acc0 = fmaf(w, base[(size_t)s * D_ + tid], acc0);
        acc1 = fmaf(w, base[(size_t)s * D_ + tid + 256], acc1);
    }
    atomicAdd(&out[b * D_ + tid], acc0);
    atomicAdd(&out[b * D_ + tid + 256], acc1);
}

// ---------------- launch ------------------------------------------------------
extern "C" void kernel_launch(void* const* d_in, const int* in_sizes, int n_in,
                              void* d_out, int out_size) {
    const float* enc = (const float*)d_in[0];
    const float* dec = (const float*)d_in[1];
    const float* W1  = (const float*)d_in[2];
    const float* b1  = (const float*)d_in[3];
    const float* W2  = (const float*)d_in[4];
    const float* b2  = (const float*)d_in[5];
    const float* V   = (const float*)d_in[6];
    // d_in[7] = bv: constant shift, cancels in softmax.
    float* out = (float*)d_out;

    w1split_kernel<<<dim3(16, 16), dim3(32, 8)>>>(W1);
    w1frag_kernel<<<8, 32>>>();
    encfrag_kernel<<<MB_CNT / 8, 256>>>(enc);
    zero_out_kernel<<<(B_ * D_ + 255) / 256, 256>>>(out);
    hd_kernel<<<B_, U_>>>(dec, W2, b2);
    score_frag_kernel<<<dim3(4, M_TOT / 128), 256>>>(b1, V);
    stats_kernel<<<B_, 256>>>();
    context_kernel<<<dim3(S_ / 128, B_), 256>>>(enc, out);
}